// round 2
// baseline (speedup 1.0000x reference)
#include <cuda_runtime.h>
#include <math.h>

#define FULLMASK 0xFFFFFFFFu

// ---------------- static device scratch (no allocation) ----------------
__device__ float d_La[1024];        // alpha logits (batch-constant)
__device__ float d_c1[128];         // baseline_b @ W1b[:1024] + b1b
__device__ float d_ctx[8192 * 32];  // per-row context after alpha selection

__device__ __forceinline__ float leaky(float x) { return x >= 0.f ? x : 0.01f * x; }

static __device__ __forceinline__ unsigned long long pack2(float x, float y) {
    unsigned long long r;
    asm("mov.b64 %0, {%1, %2};" : "=l"(r) : "f"(x), "f"(y));
    return r;
}
static __device__ __forceinline__ void unpack2(unsigned long long v, float& x, float& y) {
    asm("mov.b64 {%0, %1}, %2;" : "=f"(x), "=f"(y) : "l"(v));
}
static __device__ __forceinline__ unsigned long long fma2(unsigned long long a,
                                                          unsigned long long b,
                                                          unsigned long long c) {
    unsigned long long d;
    asm("fma.rn.f32x2 %0, %1, %2, %3;" : "=l"(d) : "l"(a), "l"(b), "l"(c));
    return d;
}

// ---------------- warp top-32-of-1024 ----------------
// Lane owns elements with global index j*32 + lane (j = 0..31), values in v[j]
// (registers only: every access uses a compile-time-constant j; exclusions are
// tracked in a bitmask, never by writing v). Iterative warp argmax with lazy
// per-lane top-2; a lane rescans its 32 values (mask-filtered) only when both
// cached candidates are consumed (~9 times per 32 rounds in expectation).
template <bool WANT_IDX>
__device__ __forceinline__ unsigned warp_select32(const float* v, int lane, int* my_gidx) {
    float m1 = -INFINITY, m2 = -INFINITY;
    int i1 = 0, i2 = 0;
#pragma unroll
    for (int j = 0; j < 32; j++) {
        float x = v[j];
        if (x > m1) { m2 = m1; i2 = i1; m1 = x; i1 = j; }
        else if (x > m2) { m2 = x; i2 = j; }
    }
    unsigned sel = 0;
#pragma unroll 1
    for (int k = 0; k < 32; k++) {
        float best = m1;
#pragma unroll
        for (int off = 16; off; off >>= 1)
            best = fmaxf(best, __shfl_xor_sync(FULLMASK, best, off));
        unsigned bal = __ballot_sync(FULLMASK, m1 == best);
        int wl = __ffs(bal) - 1;
        if (WANT_IDX) {
            int wj = __shfl_sync(FULLMASK, i1, wl);
            if (lane == k) *my_gidx = wj * 32 + wl;
        }
        if (lane == wl) {
            sel |= 1u << i1;
            m1 = m2; i1 = i2;
            m2 = -INFINITY; i2 = 0;
            if (!(m1 > -INFINITY)) {  // both consumed: masked rescan
#pragma unroll
                for (int j = 0; j < 32; j++) {
                    if (!((sel >> j) & 1)) {
                        float x = v[j];
                        if (x > m1) { m2 = m1; i2 = i1; m1 = x; i1 = j; }
                        else if (x > m2) { m2 = x; i2 = j; }
                    }
                }
            }
        }
    }
    return sel;
}

// ---------------- K1: precompute La (alpha logits) and c1 (1 block) ----------------
__global__ void kprec(const float* __restrict__ ba,
                      const float* __restrict__ W1a, const float* __restrict__ b1a,
                      const float* __restrict__ W2a, const float* __restrict__ b2a,
                      const float* __restrict__ W3a, const float* __restrict__ b3a,
                      const float* __restrict__ bb,
                      const float* __restrict__ W1b, const float* __restrict__ b1b) {
    __shared__ float h1[128];
    __shared__ float h2[64];
    int t = threadIdx.x;  // 128 threads
    {
        float p[8] = {0, 0, 0, 0, 0, 0, 0, 0};
        for (int i = 0; i < 1024; i += 8) {
#pragma unroll
            for (int j = 0; j < 8; j++) p[j] += ba[i + j] * W1a[(i + j) * 128 + t];
        }
        float s = ((p[0] + p[1]) + (p[2] + p[3])) + ((p[4] + p[5]) + (p[6] + p[7]));
        h1[t] = leaky(b1a[t] + s);
    }
    __syncthreads();
    if (t < 64) {
        float p[4] = {0, 0, 0, 0};
        for (int i = 0; i < 128; i += 4) {
#pragma unroll
            for (int j = 0; j < 4; j++) p[j] += h1[i + j] * W2a[(i + j) * 64 + t];
        }
        h2[t] = leaky(b2a[t] + (p[0] + p[1]) + (p[2] + p[3]));
    }
    __syncthreads();
    for (int o = t; o < 1024; o += 128) {
        float s = 0.f;
#pragma unroll
        for (int i = 0; i < 64; i++) s += h2[i] * W3a[i * 1024 + o];
        d_La[o] = s + b3a[o] + ba[o];
    }
    {
        float p[8] = {0, 0, 0, 0, 0, 0, 0, 0};
        for (int i = 0; i < 1024; i += 8) {
#pragma unroll
            for (int j = 0; j < 8; j++) p[j] += bb[i + j] * W1b[(i + j) * 128 + t];
        }
        float s = ((p[0] + p[1]) + (p[2] + p[3])) + ((p[4] + p[5]) + (p[6] + p[7]));
        d_c1[t] = b1b[t] + s;
    }
}

// ---------------- K2: alpha selection + ctx (1 warp / row) ----------------
__global__ __launch_bounds__(256) void kalpha(const float* __restrict__ g_alpha,
                                              const float* __restrict__ Wc,
                                              const float* __restrict__ bc,
                                              float* __restrict__ out, int B) {
    __shared__ float La_s[1024];
    for (int i = threadIdx.x; i < 1024; i += 256) La_s[i] = d_La[i];
    __syncthreads();
    int w = threadIdx.x >> 5, lane = threadIdx.x & 31;
    int row = blockIdx.x * 8 + w;
    if (row >= B) return;
    const float* g = g_alpha + (size_t)row * 1024;
    float v[32];
#pragma unroll
    for (int j = 0; j < 32; j++) v[j] = La_s[j * 32 + lane] + __ldg(g + j * 32 + lane);
    int gidx = 0;
    unsigned sel = warp_select32<true>(v, lane, &gidx);
    float* o = out + (size_t)row * 2048;
#pragma unroll
    for (int j = 0; j < 32; j++) o[j * 32 + lane] = ((sel >> j) & 1) ? 1.0f : 0.0f;
    // ctx = bc + sum of selected Wc rows (hard alpha_config forward)
    float acc = __ldg(bc + lane);
#pragma unroll
    for (int k = 0; k < 32; k++) {
        int idx = __shfl_sync(FULLMASK, gidx, k);
        acc += __ldg(Wc + (size_t)idx * 32 + lane);
    }
    d_ctx[row * 32 + lane] = acc;
}

// ---------------- K3: beta MLP (f32x2 layer 3) + selection, 16 rows/block ----------------
// dyn smem floats: ctx_s[512] | h1s[2048] | h2t[1024] | lg[16384]  (79872 B)
__global__ __launch_bounds__(256, 2) void kbeta(const float* __restrict__ g_beta,
                                                const float* __restrict__ W1b,
                                                const float* __restrict__ W2b,
                                                const float* __restrict__ b2b,
                                                const float* __restrict__ W3b,
                                                const float* __restrict__ b3b,
                                                const float* __restrict__ baseline_b,
                                                float* __restrict__ out, int B) {
    extern __shared__ float sm[];
    float* ctx_s = sm;           // 16 x 32
    float* h1s   = sm + 512;     // 16 x 128
    float* h2t   = sm + 2560;    // 64 x 16  (transposed: [o][row])
    float* lg    = sm + 3584;    // 16 x 1024
    int t = threadIdx.x;
    int row0 = blockIdx.x * 16;
    if (row0 >= B) return;

    ctx_s[t]       = d_ctx[row0 * 32 + t];
    ctx_s[256 + t] = d_ctx[row0 * 32 + 256 + t];
    __syncthreads();

    int r = t >> 4, s = t & 15;
    // layer 1: only the ctx rows of W1b matter (base_b part folded into d_c1)
    {
        float acc[8];
#pragma unroll
        for (int k = 0; k < 8; k++) acc[k] = d_c1[s + 16 * k];
        for (int i = 0; i < 32; i++) {
            float cv = ctx_s[r * 32 + i];
#pragma unroll
            for (int k = 0; k < 8; k++)
                acc[k] += cv * __ldg(&W1b[(1024 + i) * 128 + s + 16 * k]);
        }
#pragma unroll
        for (int k = 0; k < 8; k++) h1s[r * 128 + s + 16 * k] = leaky(acc[k]);
    }
    __syncthreads();
    // layer 2
    {
        float acc[4];
#pragma unroll
        for (int k = 0; k < 4; k++) acc[k] = __ldg(&b2b[s + 16 * k]);
        for (int i = 0; i < 128; i++) {
            float hv = h1s[r * 128 + i];
#pragma unroll
            for (int k = 0; k < 4; k++)
                acc[k] += hv * __ldg(&W2b[i * 64 + s + 16 * k]);
        }
#pragma unroll
        for (int k = 0; k < 4; k++) h2t[(s + 16 * k) * 16 + r] = leaky(acc[k]);
    }
    __syncthreads();
    // layer 3: thread owns 4 outputs x 16 rows, rows paired in f32x2
    {
        int o0 = t * 4;
        unsigned long long acc[32];
#pragma unroll
        for (int z = 0; z < 32; z++) acc[z] = 0ull;
#pragma unroll 4
        for (int i = 0; i < 64; i++) {
            float4 wv = __ldg((const float4*)(W3b + i * 1024 + o0));
            unsigned long long w0 = pack2(wv.x, wv.x);
            unsigned long long w1 = pack2(wv.y, wv.y);
            unsigned long long w2 = pack2(wv.z, wv.z);
            unsigned long long w3 = pack2(wv.w, wv.w);
            const float2* hp = (const float2*)(h2t + i * 16);
#pragma unroll
            for (int rp = 0; rp < 8; rp++) {
                float2 h = hp[rp];
                unsigned long long hh = pack2(h.x, h.y);
                acc[rp * 4 + 0] = fma2(w0, hh, acc[rp * 4 + 0]);
                acc[rp * 4 + 1] = fma2(w1, hh, acc[rp * 4 + 1]);
                acc[rp * 4 + 2] = fma2(w2, hh, acc[rp * 4 + 2]);
                acc[rp * 4 + 3] = fma2(w3, hh, acc[rp * 4 + 3]);
            }
        }
        float bq[4];
#pragma unroll
        for (int q = 0; q < 4; q++) bq[q] = __ldg(&b3b[o0 + q]) + __ldg(&baseline_b[o0 + q]);
#pragma unroll
        for (int rp = 0; rp < 8; rp++) {
#pragma unroll
            for (int q = 0; q < 4; q++) {
                float lo, hi;
                unpack2(acc[rp * 4 + q], lo, hi);
                lg[(rp * 2) * 1024 + o0 + q]     = lo + bq[q];
                lg[(rp * 2 + 1) * 1024 + o0 + q] = hi + bq[q];
            }
        }
    }
    __syncthreads();
    // selection: 8 warps x 2 rows
    int w = t >> 5, lane = t & 31;
#pragma unroll 1
    for (int rr = w * 2; rr < w * 2 + 2; rr++) {
        const float* g = g_beta + (size_t)(row0 + rr) * 1024;
        float v[32];
#pragma unroll
        for (int j = 0; j < 32; j++) v[j] = lg[rr * 1024 + j * 32 + lane] + __ldg(g + j * 32 + lane);
        int dummy;
        unsigned sel = warp_select32<false>(v, lane, &dummy);
        float* o = out + (size_t)(row0 + rr) * 2048 + 1024;
#pragma unroll
        for (int j = 0; j < 32; j++) o[j * 32 + lane] = ((sel >> j) & 1) ? 1.0f : 0.0f;
    }
}

// ---------------- launcher ----------------
extern "C" void kernel_launch(void* const* d_in, const int* in_sizes, int n_in,
                              void* d_out, int out_size) {
    const float* baseline_a = (const float*)d_in[0];
    const float* W1a = (const float*)d_in[1];
    const float* b1a = (const float*)d_in[2];
    const float* W2a = (const float*)d_in[3];
    const float* b2a = (const float*)d_in[4];
    const float* W3a = (const float*)d_in[5];
    const float* b3a = (const float*)d_in[6];
    const float* baseline_b = (const float*)d_in[7];
    const float* Wc  = (const float*)d_in[8];
    const float* bc  = (const float*)d_in[9];
    const float* W1b = (const float*)d_in[10];
    const float* b1b = (const float*)d_in[11];
    const float* W2b = (const float*)d_in[12];
    const float* b2b = (const float*)d_in[13];
    const float* W3b = (const float*)d_in[14];
    const float* b3b = (const float*)d_in[15];
    const float* g_alpha = (const float*)d_in[16];
    const float* g_beta  = (const float*)d_in[17];
    float* out = (float*)d_out;

    int B = in_sizes[16] / 1024;
    if (B <= 0) return;
    if (B > 8192) B = 8192;  // scratch capacity

    // idempotent, deterministic attribute set (dynamic smem > 48KB for kbeta)
    cudaFuncSetAttribute(kbeta, cudaFuncAttributeMaxDynamicSharedMemorySize, 80 * 1024);

    kprec<<<1, 128>>>(baseline_a, W1a, b1a, W2a, b2a, W3a, b3a,
                      baseline_b, W1b, b1b);
    kalpha<<<(B + 7) / 8, 256>>>(g_alpha, Wc, bc, out, B);
    kbeta<<<(B + 15) / 16, 256, 19968 * sizeof(float)>>>(
        g_beta, W1b, W2b, b2b, W3b, b3b, baseline_b, out, B);
}